// round 7
// baseline (speedup 1.0000x reference)
// MoEExperts round 7: RESUBMIT of round 6 (legacy mma.sync tf32; tcgen05 proven
// unavailable -- harness targets plain sm_100). Round-6 bench died with the same
// "container failed twice" that round 0's no-op stub produced => infra flake;
// kernel audited clean. Only trivial hardening changes.
//   * operands pre-rounded to tf32 (cvt-free GEMM inner loop)
//   * W1 column-permuted: each 128-col block = [gate64 | up64] same q-range
//     -> silu*up*routing fused into k1 epilogue via smem exchange
//   * hidden stored pre-rounded -> k3 cvt-free

#include <cuda_runtime.h>
#include <cstdint>

#define Tt 4096
#define Ee 8
#define Hh 1024
#define Qq 1024

// Scratch (__device__ globals; no allocation allowed).
__device__ float g_xr [(size_t)Tt * Hh];            //  16 MB rounded x
__device__ float g_w1p[(size_t)Ee * Hh * 2 * Qq];   //  64 MB rounded+permuted W1
__device__ float g_dnr[(size_t)Ee * Qq * Hh];       //  32 MB rounded down
__device__ float g_hid[(size_t)Tt * Ee * Qq];       // 128 MB hidden (rounded)

// ---------------------------------------------------------------- helpers
__device__ __forceinline__ unsigned smem_u32(const void* p) {
    return (unsigned)__cvta_generic_to_shared(p);
}
__device__ __forceinline__ void cp_async16(unsigned s, const void* g) {
    asm volatile("cp.async.cg.shared.global [%0], [%1], 16;\n" :: "r"(s), "l"(g));
}
__device__ __forceinline__ void cp_commit() {
    asm volatile("cp.async.commit_group;\n");
}
template<int N>
__device__ __forceinline__ void cp_wait() {
    asm volatile("cp.async.wait_group %0;\n" :: "n"(N));
}
__device__ __forceinline__ unsigned tf32_rna(float f) {
    unsigned r;
    asm("cvt.rna.tf32.f32 %0, %1;\n" : "=r"(r) : "f"(f));
    return r;
}
__device__ __forceinline__ float rnaf(float f) { return __uint_as_float(tf32_rna(f)); }

__device__ __forceinline__ void mma_tf32(float* c, const unsigned* a, const unsigned* b) {
    asm volatile(
        "mma.sync.aligned.m16n8k8.row.col.f32.tf32.tf32.f32 "
        "{%0,%1,%2,%3}, {%4,%5,%6,%7}, {%8,%9}, {%0,%1,%2,%3};\n"
        : "+f"(c[0]), "+f"(c[1]), "+f"(c[2]), "+f"(c[3])
        : "r"(a[0]), "r"(a[1]), "r"(a[2]), "r"(a[3]), "r"(b[0]), "r"(b[1]));
}

// ---------------------------------------------------------------- GEMM
// C[m0:+128, n0:+128] = A(MxK, lda) @ B(KxN, ldb), operands pre-rounded tf32.
// 256 threads, 8 warps (4m x 2n), warp tile 32x64, m16n8k8, 2-stage cp.async.
// FUSE: B is permuted W1; tile cols = [gate 0..63 | up 64..127] of one q-range;
// epilogue computes rw * silu(gate) * up, stores rounded hidden.
constexpr int BM = 128, BN = 128, BK = 16;
constexpr int APAD = 4;   // A row stride 20 floats
constexpr int BPAD = 8;   // B row stride 136 floats

union SmemT {
    struct { float As[2][BM][BK + APAD]; float Bs[2][BK][BN + BPAD]; } g;  // 37,888 B
    float ex[BM][65];                                                      // 33,280 B
};

template<bool FUSE>
__global__ __launch_bounds__(256, 2)
void gemm_tf32(const float* __restrict__ A, int lda,
               const float* __restrict__ B, int ldb, long long sBz,
               const float* __restrict__ rw,
               float* __restrict__ C, int ldc, int K)
{
    __shared__ SmemT sm;

    const int tid = threadIdx.x;
    const int m0 = blockIdx.y * BM;
    const int n0 = blockIdx.x * BN;
    const int e  = blockIdx.z;

    A += (size_t)m0 * lda;
    B += (size_t)e * sBz + n0;

    const int lane = tid & 31, warp = tid >> 5;
    const int wm = warp >> 1;        // 0..3 -> 32-row slab
    const int wn = warp & 1;         // 0..1 -> 64-col slab
    const int gid = lane >> 2;       // 0..7
    const int tig = lane & 3;        // 0..3

    auto load_stage = [&](int it, int st) {
        const int k0 = it * BK;
        #pragma unroll
        for (int i = 0; i < 2; i++) {          // A: 128 rows x 4 x 16B
            int c = tid + i * 256;
            int m = c >> 2, j = c & 3;
            cp_async16(smem_u32(&sm.g.As[st][m][j * 4]),
                       A + (size_t)m * lda + k0 + j * 4);
        }
        #pragma unroll
        for (int i = 0; i < 2; i++) {          // B: 16 rows x 32 x 16B
            int c = tid + i * 256;
            int r = c >> 5, j = c & 31;
            cp_async16(smem_u32(&sm.g.Bs[st][r][j * 4]),
                       B + (size_t)(k0 + r) * ldb + j * 4);
        }
        cp_commit();
    };

    float acc[2][8][4];
    #pragma unroll
    for (int im = 0; im < 2; im++)
        #pragma unroll
        for (int in = 0; in < 8; in++)
            #pragma unroll
            for (int v = 0; v < 4; v++) acc[im][in][v] = 0.f;

    const int nIter = K / BK;
    load_stage(0, 0);

    for (int it = 0; it < nIter; ++it) {
        const int cur = it & 1;
        if (it + 1 < nIter) { load_stage(it + 1, cur ^ 1); cp_wait<1>(); }
        else                { cp_wait<0>(); }
        __syncthreads();

        #pragma unroll
        for (int kk = 0; kk < BK; kk += 8) {
            unsigned a[2][4], bf[8][2];
            #pragma unroll
            for (int im = 0; im < 2; im++) {
                const int r = wm * 32 + im * 16 + gid;
                a[im][0] = __float_as_uint(sm.g.As[cur][r    ][kk + tig]);
                a[im][1] = __float_as_uint(sm.g.As[cur][r + 8][kk + tig]);
                a[im][2] = __float_as_uint(sm.g.As[cur][r    ][kk + tig + 4]);
                a[im][3] = __float_as_uint(sm.g.As[cur][r + 8][kk + tig + 4]);
            }
            #pragma unroll
            for (int in = 0; in < 8; in++) {
                const int nb = wn * 64 + in * 8 + gid;
                bf[in][0] = __float_as_uint(sm.g.Bs[cur][kk + tig    ][nb]);
                bf[in][1] = __float_as_uint(sm.g.Bs[cur][kk + tig + 4][nb]);
            }
            #pragma unroll
            for (int im = 0; im < 2; im++)
                #pragma unroll
                for (int in = 0; in < 8; in++)
                    mma_tf32(acc[im][in], a[im], bf[in]);
        }
        __syncthreads();
    }

    if constexpr (FUSE) {
        // wn=1 (up half) publishes accs via smem; wn=0 applies silu+rw+store.
        if (wn == 1) {
            #pragma unroll
            for (int im = 0; im < 2; im++) {
                const int r = wm * 32 + im * 16 + gid;
                #pragma unroll
                for (int in = 0; in < 8; in++) {
                    const int c = in * 8 + 2 * tig;
                    sm.ex[r    ][c]     = acc[im][in][0];
                    sm.ex[r    ][c + 1] = acc[im][in][1];
                    sm.ex[r + 8][c]     = acc[im][in][2];
                    sm.ex[r + 8][c + 1] = acc[im][in][3];
                }
            }
        }
        __syncthreads();
        if (wn == 0) {
            const int qb = blockIdx.x;                 // q-range [qb*64, +64)
            #pragma unroll
            for (int im = 0; im < 2; im++) {
                const int r = wm * 32 + im * 16 + gid;
                const int t0 = m0 + r, t1 = t0 + 8;
                const float w0 = rw[t0 * Ee + e];
                const float w1 = rw[t1 * Ee + e];
                float* H0 = C + (size_t)t0 * ldc + e * Qq + qb * 64;
                float* H1 = C + (size_t)t1 * ldc + e * Qq + qb * 64;
                #pragma unroll
                for (int in = 0; in < 8; in++) {
                    const int c = in * 8 + 2 * tig;
                    float g, u;
                    float2 o0, o1;
                    g = acc[im][in][0]; u = sm.ex[r][c];
                    o0.x = rnaf(w0 * u * (g / (1.f + __expf(-g))));
                    g = acc[im][in][1]; u = sm.ex[r][c + 1];
                    o0.y = rnaf(w0 * u * (g / (1.f + __expf(-g))));
                    g = acc[im][in][2]; u = sm.ex[r + 8][c];
                    o1.x = rnaf(w1 * u * (g / (1.f + __expf(-g))));
                    g = acc[im][in][3]; u = sm.ex[r + 8][c + 1];
                    o1.y = rnaf(w1 * u * (g / (1.f + __expf(-g))));
                    *(float2*)&H0[c] = o0;
                    *(float2*)&H1[c] = o1;
                }
            }
        }
    } else {
        C += (size_t)m0 * ldc + n0;
        #pragma unroll
        for (int im = 0; im < 2; im++) {
            const int r = wm * 32 + im * 16 + gid;
            #pragma unroll
            for (int in = 0; in < 8; in++) {
                const int col = wn * 64 + in * 8 + 2 * tig;
                *(float2*)&C[(size_t)r * ldc + col] =
                    make_float2(acc[im][in][0], acc[im][in][1]);
                *(float2*)&C[(size_t)(r + 8) * ldc + col] =
                    make_float2(acc[im][in][2], acc[im][in][3]);
            }
        }
    }
}

// ---------------------------------------------------------------- prepass
__global__ void round_copy(const float* __restrict__ src, float* __restrict__ dst)
{
    const int i = blockIdx.x * blockDim.x + threadIdx.x;
    float4 v = ((const float4*)src)[i];
    v.x = rnaf(v.x); v.y = rnaf(v.y); v.z = rnaf(v.z); v.w = rnaf(v.w);
    ((float4*)dst)[i] = v;
}

// W1 column permute + round. Out col c (block b=c>>7, i=c&127):
//   i<64  -> gate col b*64 + i ;  i>=64 -> up col 1024 + b*64 + (i-64)
__global__ void permute_w1(const float* __restrict__ src, float* __restrict__ dst)
{
    const int idx = blockIdx.x * blockDim.x + threadIdx.x;   // E*H*512 float4s
    const int c  = (idx & 511) << 2;
    const long long eh = idx >> 9;                           // e*H + h
    const int b = c >> 7, i = c & 127;
    const int srcc = (i < 64) ? b * 64 + i : 1024 + b * 64 + (i - 64);
    const float4 v = *(const float4*)&src[eh * 2048 + srcc];
    float4 o;
    o.x = rnaf(v.x); o.y = rnaf(v.y); o.z = rnaf(v.z); o.w = rnaf(v.w);
    *(float4*)&dst[eh * 2048 + c] = o;
}

// ---------------------------------------------------------------- launch
extern "C" void kernel_launch(void* const* d_in, const int* in_sizes, int n_in,
                              void* d_out, int out_size)
{
    (void)in_sizes; (void)n_in; (void)out_size;
    const float* x    = (const float*)d_in[0];   // (T, H)
    const float* rw   = (const float*)d_in[1];   // (T, E)
    const float* gup  = (const float*)d_in[2];   // (E, H, 2Q)
    const float* down = (const float*)d_in[3];   // (E, Q, H)
    float* out = (float*)d_out;                  // (T, H)

    float *xr, *w1p, *dnr, *hid;
    cudaGetSymbolAddress((void**)&xr,  g_xr);
    cudaGetSymbolAddress((void**)&w1p, g_w1p);
    cudaGetSymbolAddress((void**)&dnr, g_dnr);
    cudaGetSymbolAddress((void**)&hid, g_hid);

    // prepass: rna-round everything once
    round_copy<<<(Tt * Hh / 4) / 256, 256>>>(x, xr);
    round_copy<<<((size_t)Ee * Qq * Hh / 4) / 256, 256>>>(down, dnr);
    permute_w1<<<((size_t)Ee * Hh * 512) / 256, 256>>>(gup, w1p);

    // k1 (fused): hidden = rw * silu(gate) * up.  grid (16 q-blocks, 32 m, 8 e)
    gemm_tf32<true><<<dim3(16, 32, 8), 256>>>(
        xr, Hh, w1p, 2 * Qq, (long long)Hh * 2 * Qq, rw, hid, Ee * Qq, Hh);

    // k3: out = hidden(4096x8192) @ down(8192x1024).  grid (8, 32)
    gemm_tf32<false><<<dim3(8, 32, 1), 256>>>(
        hid, Ee * Qq, dnr, Hh, 0, nullptr, out, Hh, Ee * Qq);
}

// round 10
// speedup vs baseline: 1.4749x; 1.4749x over previous
// MoEExperts round 10: packed-fragment mma.sync tf32 on the PROVEN round-1/7
// pipeline skeleton (2-stage cp.async, explicit slot toggle, two syncthreads
// per iter) -- rounds 8/9's 3-stage/96KB variant replaced wholesale after two
// container failures. Data layout unchanged from round 8:
//   A-pack tile (16m x 8k): lane=gid*4+tig holds {A[m][2t],A[m+8][2t],A[m][2t+1],A[m+8][2t+1]}
//   B-pack tile (16n x 8k): lane holds {B[2t][n],B[2t+1][n],B[2t][n+8],B[2t+1][n+8]}
// (k-permutation kappa(tig)=2*tig on BOTH sides -> GEMM invariant.)
// Inner loop: 6 LDS.128 + 16 MMAs per kk-step. silu*up*rw fused in k1 epilogue,
// hid stored directly A-packed for k3.

#include <cuda_runtime.h>
#include <cstdint>

#define Tt 4096
#define Ee 8
#define Hh 1024
#define Qq 1024

__device__ float g_xr [(size_t)Tt * Hh];            //  16 MB packed x
__device__ float g_w1p[(size_t)Ee * Hh * 2 * Qq];   //  64 MB packed+permuted W1
__device__ float g_dnr[(size_t)Ee * Qq * Hh];       //  32 MB packed down
__device__ float g_hid[(size_t)Tt * Ee * Qq];       // 128 MB packed hidden

// ---------------------------------------------------------------- helpers
__device__ __forceinline__ unsigned smem_u32(const void* p) {
    return (unsigned)__cvta_generic_to_shared(p);
}
__device__ __forceinline__ void cp_async16(unsigned s, const void* g) {
    asm volatile("cp.async.cg.shared.global [%0], [%1], 16;\n" :: "r"(s), "l"(g));
}
__device__ __forceinline__ void cp_commit() {
    asm volatile("cp.async.commit_group;\n");
}
template<int N>
__device__ __forceinline__ void cp_wait() {
    asm volatile("cp.async.wait_group %0;\n" :: "n"(N));
}
__device__ __forceinline__ unsigned tf32_rna(float f) {
    unsigned r;
    asm("cvt.rna.tf32.f32 %0, %1;\n" : "=r"(r) : "f"(f));
    return r;
}
__device__ __forceinline__ float rnaf(float f) { return __uint_as_float(tf32_rna(f)); }

__device__ __forceinline__ void mma_tf32(float* c, const float4& a, float b0, float b1) {
    asm volatile(
        "mma.sync.aligned.m16n8k8.row.col.f32.tf32.tf32.f32 "
        "{%0,%1,%2,%3}, {%4,%5,%6,%7}, {%8,%9}, {%0,%1,%2,%3};\n"
        : "+f"(c[0]), "+f"(c[1]), "+f"(c[2]), "+f"(c[3])
        : "r"(__float_as_uint(a.x)), "r"(__float_as_uint(a.y)),
          "r"(__float_as_uint(a.z)), "r"(__float_as_uint(a.w)),
          "r"(__float_as_uint(b0)), "r"(__float_as_uint(b1)));
}

// ---------------------------------------------------------------- GEMM
// Block 128m x 128n, BK=32 (4 k-tiles of 8). 8 warps: wm(4) x wn(2), warp 32x64.
// Stage: A 8 m-tiles x 4 kt x 512B = 16KB; B same = 16KB. 2 stages = 64KB.
constexpr int STG      = 32768;
constexpr int SMEM_TOT = 2 * STG;          // 65,536 B (>= 33,280 ex buffer)

template<bool FUSE>
__global__ __launch_bounds__(256, 2)
void gemm_packed(const float4* __restrict__ A,   // packed, [mt][kt][lane]
                 const float4* __restrict__ B,   // packed, [nt][kt][lane]
                 long long sBe,                   // float4 per expert (B)
                 const float* __restrict__ rw,
                 float* __restrict__ C,           // FUSE: packed hid; else out
                 int KT)                          // K/8 tiles
{
    extern __shared__ char smem[];

    const int tid = threadIdx.x;
    const int lane = tid & 31, warp = tid >> 5;
    const int wm = warp >> 1, wn = warp & 1;
    const int gid = lane >> 2, tig = lane & 3;

    const int nb = blockIdx.x;               // n-block (128 cols)
    const int by = blockIdx.y;               // m-block (128 rows)
    const int e  = blockIdx.z;

    const float4* Ab = A + (size_t)(by * 8) * KT * 32;       // 8 m-tiles
    const float4* Bb = B + (size_t)e * sBe + (size_t)(nb * 8) * KT * 32;

    const int nIter = KT >> 2;               // BK=32 -> 4 k-tiles/iter

    auto load_stage = [&](int it, int slot) {
        char* sA = smem + slot * STG;
        char* sB = sA + 16384;
        const int ktg0 = it * 4;
        #pragma unroll
        for (int i = 0; i < 4; i++) {
            const int c = tid + i * 256;     // 0..1023
            const int mt = c >> 7, kt = (c >> 5) & 3, ln = c & 31;
            cp_async16(smem_u32(sA + ((mt * 4 + kt) * 32 + ln) * 16),
                       Ab + ((size_t)mt * KT + ktg0 + kt) * 32 + ln);
            cp_async16(smem_u32(sB + ((mt * 4 + kt) * 32 + ln) * 16),
                       Bb + ((size_t)mt * KT + ktg0 + kt) * 32 + ln);
        }
        cp_commit();
    };

    float acc[2][8][4];
    #pragma unroll
    for (int im = 0; im < 2; im++)
        #pragma unroll
        for (int in = 0; in < 8; in++)
            #pragma unroll
            for (int v = 0; v < 4; v++) acc[im][in][v] = 0.f;

    load_stage(0, 0);

    for (int it = 0; it < nIter; ++it) {
        const int cur = it & 1;
        if (it + 1 < nIter) { load_stage(it + 1, cur ^ 1); cp_wait<1>(); }
        else                { cp_wait<0>(); }
        __syncthreads();

        const char* sA = smem + cur * STG;
        const char* sB = sA + 16384;
        #pragma unroll
        for (int j = 0; j < 4; j++) {
            float4 va[2], vb[4];
            #pragma unroll
            for (int im = 0; im < 2; im++)
                va[im] = *(const float4*)(sA + (((wm * 2 + im) * 4 + j) * 32 + lane) * 16);
            #pragma unroll
            for (int p = 0; p < 4; p++)
                vb[p] = *(const float4*)(sB + (((wn * 4 + p) * 4 + j) * 32 + lane) * 16);
            #pragma unroll
            for (int im = 0; im < 2; im++)
                #pragma unroll
                for (int p = 0; p < 4; p++) {
                    mma_tf32(acc[im][2 * p],     va[im], vb[p].x, vb[p].y);
                    mma_tf32(acc[im][2 * p + 1], va[im], vb[p].z, vb[p].w);
                }
        }
        __syncthreads();
    }

    // acc[im][in] covers rows (by*128 + wm*32 + im*16 + gid, +8),
    // cols nb*128 + wn*64 + in*8 + {2tig, 2tig+1}.
    if constexpr (FUSE) {
        float (*ex)[65] = (float(*)[65])smem;  // [128][65] = 33,280 B
        if (wn == 1) {                         // publish up-half accs
            #pragma unroll
            for (int im = 0; im < 2; im++) {
                const int r = wm * 32 + im * 16 + gid;
                #pragma unroll
                for (int in = 0; in < 8; in++) {
                    const int c = in * 8 + 2 * tig;
                    ex[r    ][c]     = acc[im][in][0];
                    ex[r    ][c + 1] = acc[im][in][1];
                    ex[r + 8][c]     = acc[im][in][2];
                    ex[r + 8][c + 1] = acc[im][in][3];
                }
            }
        }
        __syncthreads();
        if (wn == 0) {                         // silu + rw, store packed hid
            #pragma unroll
            for (int im = 0; im < 2; im++) {
                const int r = wm * 32 + im * 16 + gid;
                const int t0 = by * 128 + r;
                const float w0 = rw[t0 * Ee + e];
                const float w1 = rw[(t0 + 8) * Ee + e];
                const size_t mt = (size_t)(by * 8 + wm * 2 + im);
                #pragma unroll
                for (int in = 0; in < 8; in++) {
                    const int c = in * 8 + 2 * tig;
                    float g, u, v0, v1, v2, v3;
                    g = acc[im][in][0]; u = ex[r][c];
                    v0 = rnaf(w0 * u * (g / (1.f + __expf(-g))));
                    g = acc[im][in][1]; u = ex[r][c + 1];
                    v1 = rnaf(w0 * u * (g / (1.f + __expf(-g))));
                    g = acc[im][in][2]; u = ex[r + 8][c];
                    v2 = rnaf(w1 * u * (g / (1.f + __expf(-g))));
                    g = acc[im][in][3]; u = ex[r + 8][c + 1];
                    v3 = rnaf(w1 * u * (g / (1.f + __expf(-g))));
                    // packed-A store for k3: slots {(t0,q),(t0+8,q),(t0,q+1),(t0+8,q+1)}
                    const size_t ktq = (size_t)(e * 128 + nb * 8 + in);
                    ((float4*)C)[(mt * 1024 + ktq) * 32 + lane] =
                        make_float4(v0, v2, v1, v3);
                }
            }
        }
    } else {
        #pragma unroll
        for (int im = 0; im < 2; im++) {
            const int r = wm * 32 + im * 16 + gid;
            const int t0 = by * 128 + r;
            #pragma unroll
            for (int in = 0; in < 8; in++) {
                const int col = nb * 128 + wn * 64 + in * 8 + 2 * tig;
                *(float2*)&C[(size_t)t0 * Hh + col] =
                    make_float2(acc[im][in][0], acc[im][in][1]);
                *(float2*)&C[(size_t)(t0 + 8) * Hh + col] =
                    make_float2(acc[im][in][2], acc[im][in][3]);
            }
        }
    }
}

// ---------------------------------------------------------------- prepass
// pack_a: x (4096x1024) -> A-packed xr. One float4 out per thread.
__global__ void pack_a(const float* __restrict__ x, float4* __restrict__ dst)
{
    const int idx = blockIdx.x * blockDim.x + threadIdx.x;   // 2^20
    const int lane = idx & 31, kt = (idx >> 5) & 127, mt = idx >> 12;
    const int gid = lane >> 2, tig = lane & 3;
    const int m = mt * 16 + gid, k = kt * 8 + 2 * tig;
    const float2 p0 = *(const float2*)&x[(size_t)m * 1024 + k];
    const float2 p1 = *(const float2*)&x[(size_t)(m + 8) * 1024 + k];
    dst[idx] = make_float4(rnaf(p0.x), rnaf(p1.x), rnaf(p0.y), rnaf(p1.y));
}

// pack_w1: gup (E,H,2Q) -> B-packed w1p in permuted n' space:
//   n' = nb*128 + i : i<64 -> gate col nb*64+i ; i>=64 -> up col 1024+nb*64+i-64
__global__ void pack_w1(const float* __restrict__ gup, float4* __restrict__ dst)
{
    const int idx = blockIdx.x * blockDim.x + threadIdx.x;   // 2^22
    const int lane = idx & 31, kt = (idx >> 5) & 127, nt = (idx >> 12) & 127;
    const int e = idx >> 19;
    const int gid = lane >> 2, tig = lane & 3;
    const int k = kt * 8 + 2 * tig;
    auto orig = [](int np) {
        const int b = np >> 7, i = np & 127;
        return (i < 64) ? b * 64 + i : 1024 + b * 64 + (i - 64);
    };
    const int oA = orig(nt * 16 + gid), oB = orig(nt * 16 + 8 + gid);
    const float* r0 = gup + ((size_t)(e << 10) + k) * 2048;
    const float* r1 = r0 + 2048;
    dst[idx] = make_float4(rnaf(r0[oA]), rnaf(r1[oA]), rnaf(r0[oB]), rnaf(r1[oB]));
}

// pack_dn: down (E,Q,H) -> B-packed dnr, k = e*1024+q (N=1024, K=8192).
__global__ void pack_dn(const float* __restrict__ dn, float4* __restrict__ dst)
{
    const int idx = blockIdx.x * blockDim.x + threadIdx.x;   // 2^21
    const int lane = idx & 31, kt = (idx >> 5) & 1023, nt = idx >> 15;
    const int gid = lane >> 2, tig = lane & 3;
    const int k = kt * 8 + 2 * tig;
    const int n = nt * 16 + gid;
    const float* r0 = dn + (size_t)k * 1024;         // (e<<10)+q == k
    const float* r1 = r0 + 1024;
    dst[idx] = make_float4(rnaf(r0[n]), rnaf(r1[n]), rnaf(r0[n + 8]), rnaf(r1[n + 8]));
}

// ---------------------------------------------------------------- launch
extern "C" void kernel_launch(void* const* d_in, const int* in_sizes, int n_in,
                              void* d_out, int out_size)
{
    (void)in_sizes; (void)n_in; (void)out_size;
    const float* x    = (const float*)d_in[0];   // (T, H)
    const float* rw   = (const float*)d_in[1];   // (T, E)
    const float* gup  = (const float*)d_in[2];   // (E, H, 2Q)
    const float* down = (const float*)d_in[3];   // (E, Q, H)
    float* out = (float*)d_out;                  // (T, H)

    float *xr, *w1p, *dnr, *hid;
    cudaGetSymbolAddress((void**)&xr,  g_xr);
    cudaGetSymbolAddress((void**)&w1p, g_w1p);
    cudaGetSymbolAddress((void**)&dnr, g_dnr);
    cudaGetSymbolAddress((void**)&hid, g_hid);

    cudaFuncSetAttribute(gemm_packed<true>,
                         cudaFuncAttributeMaxDynamicSharedMemorySize, SMEM_TOT);
    cudaFuncSetAttribute(gemm_packed<false>,
                         cudaFuncAttributeMaxDynamicSharedMemorySize, SMEM_TOT);

    pack_a <<<4096,  256>>>(x, (float4*)xr);
    pack_w1<<<16384, 256>>>(gup, (float4*)w1p);
    pack_dn<<<8192,  256>>>(down, (float4*)dnr);

    // k1: hidden = rw * silu(gate) * up (fused, packed store). KT=128.
    gemm_packed<true><<<dim3(16, 32, 8), 256, SMEM_TOT>>>(
        (const float4*)xr, (const float4*)w1p, 524288LL, rw, hid, 128);

    // k3: out = hid(4096x8192) @ dnr^T. KT=1024.
    gemm_packed<false><<<dim3(8, 32, 1), 256, SMEM_TOT>>>(
        (const float4*)hid, (const float4*)dnr, 0LL, nullptr, out, 1024);
}

// round 11
// speedup vs baseline: 1.4915x; 1.0113x over previous
// MoEExperts round 11: packed-fragment mma.sync tf32, refactored for finer
// concurrency: 128-thread CTAs (4 warps, tile 128x64), 4 CTAs/SM, ONE
// __syncthreads per iteration, register-local silu epilogue (gate/up
// interleaved at 32-col granularity -> same warp holds both halves).
// Packed layouts unchanged from round 10 (k-perm kappa(tig)=2*tig both sides).

#include <cuda_runtime.h>
#include <cstdint>

#define Tt 4096
#define Ee 8
#define Hh 1024
#define Qq 1024

__device__ float g_xr [(size_t)Tt * Hh];            //  16 MB packed x
__device__ float g_w1p[(size_t)Ee * Hh * 2 * Qq];   //  64 MB packed+permuted W1
__device__ float g_dnr[(size_t)Ee * Qq * Hh];       //  32 MB packed down
__device__ float g_hid[(size_t)Tt * Ee * Qq];       // 128 MB packed hidden

// ---------------------------------------------------------------- helpers
__device__ __forceinline__ unsigned smem_u32(const void* p) {
    return (unsigned)__cvta_generic_to_shared(p);
}
__device__ __forceinline__ void cp_async16(unsigned s, const void* g) {
    asm volatile("cp.async.cg.shared.global [%0], [%1], 16;\n" :: "r"(s), "l"(g));
}
__device__ __forceinline__ void cp_commit() {
    asm volatile("cp.async.commit_group;\n");
}
template<int N>
__device__ __forceinline__ void cp_wait() {
    asm volatile("cp.async.wait_group %0;\n" :: "n"(N));
}
__device__ __forceinline__ unsigned tf32_rna(float f) {
    unsigned r;
    asm("cvt.rna.tf32.f32 %0, %1;\n" : "=r"(r) : "f"(f));
    return r;
}
__device__ __forceinline__ float rnaf(float f) { return __uint_as_float(tf32_rna(f)); }

__device__ __forceinline__ void mma_tf32(float* c, const float4& a, float b0, float b1) {
    asm volatile(
        "mma.sync.aligned.m16n8k8.row.col.f32.tf32.tf32.f32 "
        "{%0,%1,%2,%3}, {%4,%5,%6,%7}, {%8,%9}, {%0,%1,%2,%3};\n"
        : "+f"(c[0]), "+f"(c[1]), "+f"(c[2]), "+f"(c[3])
        : "r"(__float_as_uint(a.x)), "r"(__float_as_uint(a.y)),
          "r"(__float_as_uint(a.z)), "r"(__float_as_uint(a.w)),
          "r"(__float_as_uint(b0)), "r"(__float_as_uint(b1)));
}

// ---------------------------------------------------------------- GEMM
// Block tile 128m x 64n, BK=32 (4 k-tiles of 8). 4 warps: wm in [0,4), warp
// tile 32x64 (full N). Stage: A 8 mt x 4 kt x 512B = 16KB; B 4 nt x 4 kt x
// 512B = 8KB. 2 stages = 48KB dyn smem; 4 CTAs/SM.
constexpr int STG      = 24576;
constexpr int SMEM_TOT = 2 * STG;          // 49,152 B

template<bool FUSE>
__global__ __launch_bounds__(128, 4)
void gemm_packed(const float4* __restrict__ A,   // packed, [mt][kt][lane]
                 const float4* __restrict__ B,   // packed, [nt][kt][lane]
                 long long sBe,                   // float4 per expert (B)
                 const float* __restrict__ rw,
                 float* __restrict__ C,           // FUSE: packed hid; else out
                 int KT)                          // K/8 tiles
{
    extern __shared__ char smem[];

    const int tid = threadIdx.x;
    const int lane = tid & 31, wm = tid >> 5;     // 4 warps, all-M split
    const int gid = lane >> 2, tig = lane & 3;

    const int nb = blockIdx.x;               // n-block (64 cols)
    const int by = blockIdx.y;               // m-block (128 rows)
    const int e  = blockIdx.z;

    const float4* Ab = A + (size_t)(by * 8) * KT * 32;       // 8 m-tiles
    const float4* Bb = B + (size_t)e * sBe + (size_t)(nb * 4) * KT * 32;

    const int nIter = KT >> 2;               // BK=32 -> 4 k-tiles/iter

    auto load_stage = [&](int it, int slot) {
        char* sA = smem + slot * STG;
        char* sB = sA + 16384;
        const int ktg0 = it * 4;
        #pragma unroll
        for (int i = 0; i < 8; i++) {        // A: 1024 float4
            const int c = tid + i * 128;
            const int mt = c >> 7, kt = (c >> 5) & 3, ln = c & 31;
            cp_async16(smem_u32(sA + ((mt * 4 + kt) * 32 + ln) * 16),
                       Ab + ((size_t)mt * KT + ktg0 + kt) * 32 + ln);
        }
        #pragma unroll
        for (int i = 0; i < 4; i++) {        // B: 512 float4
            const int c = tid + i * 128;
            const int nt = c >> 7, kt = (c >> 5) & 3, ln = c & 31;
            cp_async16(smem_u32(sB + ((nt * 4 + kt) * 32 + ln) * 16),
                       Bb + ((size_t)nt * KT + ktg0 + kt) * 32 + ln);
        }
        cp_commit();
    };

    float acc[2][8][4];
    #pragma unroll
    for (int im = 0; im < 2; im++)
        #pragma unroll
        for (int in = 0; in < 8; in++)
            #pragma unroll
            for (int v = 0; v < 4; v++) acc[im][in][v] = 0.f;

    load_stage(0, 0);

    for (int it = 0; it < nIter; ++it) {
        const int cur = it & 1;
        cp_wait<0>();                        // stage `it` (only group in flight)
        __syncthreads();                     // + all warps done reading slot cur^1
        if (it + 1 < nIter) load_stage(it + 1, cur ^ 1);

        const char* sA = smem + cur * STG;
        const char* sB = sA + 16384;
        #pragma unroll
        for (int j = 0; j < 4; j++) {
            float4 va[2], vb[4];
            #pragma unroll
            for (int im = 0; im < 2; im++)
                va[im] = *(const float4*)(sA + (((wm * 2 + im) * 4 + j) * 32 + lane) * 16);
            #pragma unroll
            for (int p = 0; p < 4; p++)
                vb[p] = *(const float4*)(sB + ((p * 4 + j) * 32 + lane) * 16);
            #pragma unroll
            for (int im = 0; im < 2; im++)
                #pragma unroll
                for (int p = 0; p < 4; p++) {
                    mma_tf32(acc[im][2 * p],     va[im], vb[p].x, vb[p].y);
                    mma_tf32(acc[im][2 * p + 1], va[im], vb[p].z, vb[p].w);
                }
        }
    }
    // No post-loop barrier needed: epilogue uses no shared memory.

    // acc[im][in] covers rows (by*128 + wm*32 + im*16 + gid, +8),
    // cols nb*64 + in*8 + {2tig, 2tig+1}. FUSE: cols [0,32)=gate, [32,64)=up
    // for q-range nb*32..+32 (same-thread gate/up pairs: acc[in] vs acc[in+4]).
    if constexpr (FUSE) {
        #pragma unroll
        for (int im = 0; im < 2; im++) {
            const int r = wm * 32 + im * 16 + gid;
            const int t0 = by * 128 + r;
            const float w0 = rw[t0 * Ee + e];
            const float w1 = rw[(t0 + 8) * Ee + e];
            const size_t mt = (size_t)(by * 8 + wm * 2 + im);
            #pragma unroll
            for (int in = 0; in < 4; in++) {
                float g, u, v0, v1, v2, v3;
                g = acc[im][in][0]; u = acc[im][in + 4][0];
                v0 = rnaf(w0 * u * (g / (1.f + __expf(-g))));
                g = acc[im][in][1]; u = acc[im][in + 4][1];
                v1 = rnaf(w0 * u * (g / (1.f + __expf(-g))));
                g = acc[im][in][2]; u = acc[im][in + 4][2];
                v2 = rnaf(w1 * u * (g / (1.f + __expf(-g))));
                g = acc[im][in][3]; u = acc[im][in + 4][3];
                v3 = rnaf(w1 * u * (g / (1.f + __expf(-g))));
                // packed-A store for k3: lane holds {(t0,q),(t0+8,q),(t0,q+1),(t0+8,q+1)}
                const size_t ktq = (size_t)(e * 128 + nb * 4 + in);
                ((float4*)C)[(mt * 1024 + ktq) * 32 + lane] =
                    make_float4(v0, v2, v1, v3);
            }
        }
    } else {
        #pragma unroll
        for (int im = 0; im < 2; im++) {
            const int r = wm * 32 + im * 16 + gid;
            const int t0 = by * 128 + r;
            #pragma unroll
            for (int in = 0; in < 8; in++) {
                const int col = nb * 64 + in * 8 + 2 * tig;
                *(float2*)&C[(size_t)t0 * Hh + col] =
                    make_float2(acc[im][in][0], acc[im][in][1]);
                *(float2*)&C[(size_t)(t0 + 8) * Hh + col] =
                    make_float2(acc[im][in][2], acc[im][in][3]);
            }
        }
    }
}

// ---------------------------------------------------------------- prepass
// pack_a: x (4096x1024) -> A-packed xr. One float4 out per thread.
__global__ void pack_a(const float* __restrict__ x, float4* __restrict__ dst)
{
    const int idx = blockIdx.x * blockDim.x + threadIdx.x;   // 2^20
    const int lane = idx & 31, kt = (idx >> 5) & 127, mt = idx >> 12;
    const int gid = lane >> 2, tig = lane & 3;
    const int m = mt * 16 + gid, k = kt * 8 + 2 * tig;
    const float2 p0 = *(const float2*)&x[(size_t)m * 1024 + k];
    const float2 p1 = *(const float2*)&x[(size_t)(m + 8) * 1024 + k];
    dst[idx] = make_float4(rnaf(p0.x), rnaf(p1.x), rnaf(p0.y), rnaf(p1.y));
}

// pack_w1: gup (E,H,2Q) -> B-packed w1p in permuted n' space (32-granular):
//   n' = b*64 + i, b in [0,32): i<32 -> gate col b*32+i ; i>=32 -> up col
//   1024 + b*32 + (i-32).  (Each 64-block = [gate32|up32] of one q-range.)
__global__ void pack_w1(const float* __restrict__ gup, float4* __restrict__ dst)
{
    const int idx = blockIdx.x * blockDim.x + threadIdx.x;   // 2^22
    const int lane = idx & 31, kt = (idx >> 5) & 127, nt = (idx >> 12) & 127;
    const int e = idx >> 19;
    const int gid = lane >> 2, tig = lane & 3;
    const int k = kt * 8 + 2 * tig;
    auto orig = [](int np) {
        const int b = np >> 6, i = np & 63;
        return (i < 32) ? b * 32 + i : 1024 + b * 32 + (i - 32);
    };
    const int oA = orig(nt * 16 + gid), oB = orig(nt * 16 + 8 + gid);
    const float* r0 = gup + ((size_t)(e << 10) + k) * 2048;
    const float* r1 = r0 + 2048;
    dst[idx] = make_float4(rnaf(r0[oA]), rnaf(r1[oA]), rnaf(r0[oB]), rnaf(r1[oB]));
}

// pack_dn: down (E,Q,H) -> B-packed dnr, k = e*1024+q (N=1024, K=8192).
__global__ void pack_dn(const float* __restrict__ dn, float4* __restrict__ dst)
{
    const int idx = blockIdx.x * blockDim.x + threadIdx.x;   // 2^21
    const int lane = idx & 31, kt = (idx >> 5) & 1023, nt = idx >> 15;
    const int gid = lane >> 2, tig = lane & 3;
    const int k = kt * 8 + 2 * tig;
    const int n = nt * 16 + gid;
    const float* r0 = dn + (size_t)k * 1024;         // (e<<10)+q == k
    const float* r1 = r0 + 1024;
    dst[idx] = make_float4(rnaf(r0[n]), rnaf(r1[n]), rnaf(r0[n + 8]), rnaf(r1[n + 8]));
}

// ---------------------------------------------------------------- launch
extern "C" void kernel_launch(void* const* d_in, const int* in_sizes, int n_in,
                              void* d_out, int out_size)
{
    (void)in_sizes; (void)n_in; (void)out_size;
    const float* x    = (const float*)d_in[0];   // (T, H)
    const float* rw   = (const float*)d_in[1];   // (T, E)
    const float* gup  = (const float*)d_in[2];   // (E, H, 2Q)
    const float* down = (const float*)d_in[3];   // (E, Q, H)
    float* out = (float*)d_out;                  // (T, H)

    float *xr, *w1p, *dnr, *hid;
    cudaGetSymbolAddress((void**)&xr,  g_xr);
    cudaGetSymbolAddress((void**)&w1p, g_w1p);
    cudaGetSymbolAddress((void**)&dnr, g_dnr);
    cudaGetSymbolAddress((void**)&hid, g_hid);

    cudaFuncSetAttribute(gemm_packed<true>,
                         cudaFuncAttributeMaxDynamicSharedMemorySize, SMEM_TOT);
    cudaFuncSetAttribute(gemm_packed<false>,
                         cudaFuncAttributeMaxDynamicSharedMemorySize, SMEM_TOT);

    pack_a <<<4096,  256>>>(x, (float4*)xr);
    pack_w1<<<16384, 256>>>(gup, (float4*)w1p);
    pack_dn<<<8192,  256>>>(down, (float4*)dnr);

    // k1: hidden = rw * silu(gate) * up (fused, packed store). KT=128.
    // grid: 32 n-blocks (64 n'-cols each) x 32 m-blocks x 8 experts.
    gemm_packed<true><<<dim3(32, 32, 8), 128, SMEM_TOT>>>(
        (const float4*)xr, (const float4*)w1p, 524288LL, rw, hid, 128);

    // k3: out = hid(4096x8192) @ dnr^T. KT=1024. grid (16, 32).
    gemm_packed<false><<<dim3(16, 32, 1), 128, SMEM_TOT>>>(
        (const float4*)hid, (const float4*)dnr, 0LL, nullptr, out, 1024);
}

// round 12
// speedup vs baseline: 1.5208x; 1.0196x over previous
// MoEExperts round 12: packed-fragment mma.sync tf32, warp tile 64x64
// (CTA 128x128, 4 warps 2x2, 2 CTAs/SM). Cuts LDS bytes/MMA 192->128 and
// fill/MMA 96->64: smem crossbar (the round-11 binder) load factor -> 0.75.
// Single __syncthreads per iteration; register-local silu epilogue via
// 32-granular [gate32|up32] W1 interleave. Packed layouts as rounds 10/11.

#include <cuda_runtime.h>
#include <cstdint>

#define Tt 4096
#define Ee 8
#define Hh 1024
#define Qq 1024

__device__ float g_xr [(size_t)Tt * Hh];            //  16 MB packed x
__device__ float g_w1p[(size_t)Ee * Hh * 2 * Qq];   //  64 MB packed+permuted W1
__device__ float g_dnr[(size_t)Ee * Qq * Hh];       //  32 MB packed down
__device__ float g_hid[(size_t)Tt * Ee * Qq];       // 128 MB packed hidden

// ---------------------------------------------------------------- helpers
__device__ __forceinline__ unsigned smem_u32(const void* p) {
    return (unsigned)__cvta_generic_to_shared(p);
}
__device__ __forceinline__ void cp_async16(unsigned s, const void* g) {
    asm volatile("cp.async.cg.shared.global [%0], [%1], 16;\n" :: "r"(s), "l"(g));
}
__device__ __forceinline__ void cp_commit() {
    asm volatile("cp.async.commit_group;\n");
}
template<int N>
__device__ __forceinline__ void cp_wait() {
    asm volatile("cp.async.wait_group %0;\n" :: "n"(N));
}
__device__ __forceinline__ unsigned tf32_rna(float f) {
    unsigned r;
    asm("cvt.rna.tf32.f32 %0, %1;\n" : "=r"(r) : "f"(f));
    return r;
}
__device__ __forceinline__ float rnaf(float f) { return __uint_as_float(tf32_rna(f)); }

__device__ __forceinline__ void mma_tf32(float* c, const float4& a, float b0, float b1) {
    asm volatile(
        "mma.sync.aligned.m16n8k8.row.col.f32.tf32.tf32.f32 "
        "{%0,%1,%2,%3}, {%4,%5,%6,%7}, {%8,%9}, {%0,%1,%2,%3};\n"
        : "+f"(c[0]), "+f"(c[1]), "+f"(c[2]), "+f"(c[3])
        : "r"(__float_as_uint(a.x)), "r"(__float_as_uint(a.y)),
          "r"(__float_as_uint(a.z)), "r"(__float_as_uint(a.w)),
          "r"(__float_as_uint(b0)), "r"(__float_as_uint(b1)));
}

// ---------------------------------------------------------------- GEMM
// CTA tile 128m x 128n, BK=32 (4 k-tiles of 8). 4 warps 2x2, warp tile 64x64.
// Stage: A 8 mt x 4 kt x 512B = 16KB; B 8 nt x 4 kt x 512B = 16KB.
constexpr int STG      = 32768;
constexpr int SMEM_TOT = 2 * STG;          // 65,536 B -> 2 CTAs/SM

template<bool FUSE>
__global__ __launch_bounds__(128, 2)
void gemm_packed(const float4* __restrict__ A,   // packed, [mt][kt][lane]
                 const float4* __restrict__ B,   // packed, [nt][kt][lane]
                 long long sBe,                   // float4 per expert (B)
                 const float* __restrict__ rw,
                 float* __restrict__ C,           // FUSE: packed hid; else out
                 int KT)                          // K/8 tiles
{
    extern __shared__ char smem[];

    const int tid = threadIdx.x;
    const int lane = tid & 31, warp = tid >> 5;
    const int wm = warp >> 1, wn = warp & 1;      // 2x2 warp grid
    const int gid = lane >> 2, tig = lane & 3;

    const int nb = blockIdx.x;               // n-block (128 cols)
    const int by = blockIdx.y;               // m-block (128 rows)
    const int e  = blockIdx.z;

    const float4* Ab = A + (size_t)(by * 8) * KT * 32;       // 8 m-tiles
    const float4* Bb = B + (size_t)e * sBe + (size_t)(nb * 8) * KT * 32;

    const int nIter = KT >> 2;               // BK=32 -> 4 k-tiles/iter

    auto load_stage = [&](int it, int slot) {
        char* sA = smem + slot * STG;
        char* sB = sA + 16384;
        const int ktg0 = it * 4;
        #pragma unroll
        for (int i = 0; i < 8; i++) {        // A: 1024 float4
            const int c = tid + i * 128;
            const int mt = c >> 7, kt = (c >> 5) & 3, ln = c & 31;
            cp_async16(smem_u32(sA + ((mt * 4 + kt) * 32 + ln) * 16),
                       Ab + ((size_t)mt * KT + ktg0 + kt) * 32 + ln);
        }
        #pragma unroll
        for (int i = 0; i < 8; i++) {        // B: 1024 float4
            const int c = tid + i * 128;
            const int nt = c >> 7, kt = (c >> 5) & 3, ln = c & 31;
            cp_async16(smem_u32(sB + ((nt * 4 + kt) * 32 + ln) * 16),
                       Bb + ((size_t)nt * KT + ktg0 + kt) * 32 + ln);
        }
        cp_commit();
    };

    float acc[4][8][4];                      // 128 regs: 4 m-tiles x 8 n-cols
    #pragma unroll
    for (int im = 0; im < 4; im++)
        #pragma unroll
        for (int in = 0; in < 8; in++)
            #pragma unroll
            for (int v = 0; v < 4; v++) acc[im][in][v] = 0.f;

    load_stage(0, 0);

    for (int it = 0; it < nIter; ++it) {
        const int cur = it & 1;
        cp_wait<0>();                        // stage `it` complete
        __syncthreads();                     // + all warps done with slot cur^1
        if (it + 1 < nIter) load_stage(it + 1, cur ^ 1);

        const char* sA = smem + cur * STG;
        const char* sB = sA + 16384;
        #pragma unroll
        for (int j = 0; j < 4; j++) {
            float4 va[4], vb[4];
            #pragma unroll
            for (int im = 0; im < 4; im++)
                va[im] = *(const float4*)(sA + (((wm * 4 + im) * 4 + j) * 32 + lane) * 16);
            #pragma unroll
            for (int p = 0; p < 4; p++)
                vb[p] = *(const float4*)(sB + (((wn * 4 + p) * 4 + j) * 32 + lane) * 16);
            #pragma unroll
            for (int im = 0; im < 4; im++)
                #pragma unroll
                for (int p = 0; p < 4; p++) {
                    mma_tf32(acc[im][2 * p],     va[im], vb[p].x, vb[p].y);
                    mma_tf32(acc[im][2 * p + 1], va[im], vb[p].z, vb[p].w);
                }
        }
    }
    // Epilogue uses no shared memory: no trailing barrier needed.

    // acc[im][in]: rows by*128 + wm*64 + im*16 + gid (+8),
    // cols nb*128 + wn*64 + in*8 + {2tig, 2tig+1}.
    // FUSE: each 64-block = [gate32|up32] of q-range (nb*2+wn)*32:
    //   in 0..3 = gate, in+4 = up (same thread, same rows) -> register-local.
    if constexpr (FUSE) {
        #pragma unroll
        for (int im = 0; im < 4; im++) {
            const int r = wm * 64 + im * 16 + gid;
            const int t0 = by * 128 + r;
            const float w0 = rw[t0 * Ee + e];
            const float w1 = rw[(t0 + 8) * Ee + e];
            const size_t mt = (size_t)(by * 8 + wm * 4 + im);
            #pragma unroll
            for (int in = 0; in < 4; in++) {
                float g, u, v0, v1, v2, v3;
                g = acc[im][in][0]; u = acc[im][in + 4][0];
                v0 = rnaf(w0 * u * (g / (1.f + __expf(-g))));
                g = acc[im][in][1]; u = acc[im][in + 4][1];
                v1 = rnaf(w0 * u * (g / (1.f + __expf(-g))));
                g = acc[im][in][2]; u = acc[im][in + 4][2];
                v2 = rnaf(w1 * u * (g / (1.f + __expf(-g))));
                g = acc[im][in][3]; u = acc[im][in + 4][3];
                v3 = rnaf(w1 * u * (g / (1.f + __expf(-g))));
                // packed-A store for k3: {(t0,q),(t0+8,q),(t0,q+1),(t0+8,q+1)}
                const size_t ktq = (size_t)(e * 128 + (nb * 2 + wn) * 4 + in);
                ((float4*)C)[(mt * 1024 + ktq) * 32 + lane] =
                    make_float4(v0, v2, v1, v3);
            }
        }
    } else {
        #pragma unroll
        for (int im = 0; im < 4; im++) {
            const int r = wm * 64 + im * 16 + gid;
            const int t0 = by * 128 + r;
            #pragma unroll
            for (int in = 0; in < 8; in++) {
                const int col = nb * 128 + wn * 64 + in * 8 + 2 * tig;
                *(float2*)&C[(size_t)t0 * Hh + col] =
                    make_float2(acc[im][in][0], acc[im][in][1]);
                *(float2*)&C[(size_t)(t0 + 8) * Hh + col] =
                    make_float2(acc[im][in][2], acc[im][in][3]);
            }
        }
    }
}

// ---------------------------------------------------------------- prepass
// pack_a: x (4096x1024) -> A-packed xr. One float4 out per thread.
__global__ void pack_a(const float* __restrict__ x, float4* __restrict__ dst)
{
    const int idx = blockIdx.x * blockDim.x + threadIdx.x;   // 2^20
    const int lane = idx & 31, kt = (idx >> 5) & 127, mt = idx >> 12;
    const int gid = lane >> 2, tig = lane & 3;
    const int m = mt * 16 + gid, k = kt * 8 + 2 * tig;
    const float2 p0 = *(const float2*)&x[(size_t)m * 1024 + k];
    const float2 p1 = *(const float2*)&x[(size_t)(m + 8) * 1024 + k];
    dst[idx] = make_float4(rnaf(p0.x), rnaf(p1.x), rnaf(p0.y), rnaf(p1.y));
}

// pack_w1: gup (E,H,2Q) -> B-packed w1p, 32-granular interleave:
//   n' = b*64 + i, b in [0,32): i<32 -> gate col b*32+i ; i>=32 -> up col
//   1024 + b*32 + (i-32).  (Each 64-block = [gate32|up32] of one q-range.)
__global__ void pack_w1(const float* __restrict__ gup, float4* __restrict__ dst)
{
    const int idx = blockIdx.x * blockDim.x + threadIdx.x;   // 2^22
    const int lane = idx & 31, kt = (idx >> 5) & 127, nt = (idx >> 12) & 127;
    const int e = idx >> 19;
    const int gid = lane >> 2, tig = lane & 3;
    const int k = kt * 8 + 2 * tig;
    auto orig = [](int np) {
        const int b = np >> 6, i = np & 63;
        return (i < 32) ? b * 32 + i : 1024 + b * 32 + (i - 32);
    };
    const int oA = orig(nt * 16 + gid), oB = orig(nt * 16 + 8 + gid);
    const float* r0 = gup + ((size_t)(e << 10) + k) * 2048;
    const float* r1 = r0 + 2048;
    dst[idx] = make_float4(rnaf(r0[oA]), rnaf(r1[oA]), rnaf(r0[oB]), rnaf(r1[oB]));
}

// pack_dn: down (E,Q,H) -> B-packed dnr, k = e*1024+q (N=1024, K=8192).
__global__ void pack_dn(const float* __restrict__ dn, float4* __restrict__ dst)
{
    const int idx = blockIdx.x * blockDim.x + threadIdx.x;   // 2^21
    const int lane = idx & 31, kt = (idx >> 5) & 1023, nt = idx >> 15;
    const int gid = lane >> 2, tig = lane & 3;
    const int k = kt * 8 + 2 * tig;
    const int n = nt * 16 + gid;
    const float* r0 = dn + (size_t)k * 1024;         // (e<<10)+q == k
    const float* r1 = r0 + 1024;
    dst[idx] = make_float4(rnaf(r0[n]), rnaf(r1[n]), rnaf(r0[n + 8]), rnaf(r1[n + 8]));
}

// ---------------------------------------------------------------- launch
extern "C" void kernel_launch(void* const* d_in, const int* in_sizes, int n_in,
                              void* d_out, int out_size)
{
    (void)in_sizes; (void)n_in; (void)out_size;
    const float* x    = (const float*)d_in[0];   // (T, H)
    const float* rw   = (const float*)d_in[1];   // (T, E)
    const float* gup  = (const float*)d_in[2];   // (E, H, 2Q)
    const float* down = (const float*)d_in[3];   // (E, Q, H)
    float* out = (float*)d_out;                  // (T, H)

    float *xr, *w1p, *dnr, *hid;
    cudaGetSymbolAddress((void**)&xr,  g_xr);
    cudaGetSymbolAddress((void**)&w1p, g_w1p);
    cudaGetSymbolAddress((void**)&dnr, g_dnr);
    cudaGetSymbolAddress((void**)&hid, g_hid);

    cudaFuncSetAttribute(gemm_packed<true>,
                         cudaFuncAttributeMaxDynamicSharedMemorySize, SMEM_TOT);
    cudaFuncSetAttribute(gemm_packed<false>,
                         cudaFuncAttributeMaxDynamicSharedMemorySize, SMEM_TOT);

    pack_a <<<4096,  256>>>(x, (float4*)xr);
    pack_w1<<<16384, 256>>>(gup, (float4*)w1p);
    pack_dn<<<8192,  256>>>(down, (float4*)dnr);

    // k1: hidden = rw * silu(gate) * up (fused, packed store). KT=128.
    // grid: 16 n-blocks (128 n'-cols) x 32 m-blocks x 8 experts.
    gemm_packed<true><<<dim3(16, 32, 8), 128, SMEM_TOT>>>(
        (const float4*)xr, (const float4*)w1p, 524288LL, rw, hid, 128);

    // k3: out = hid(4096x8192) @ dnr^T. KT=1024. grid (8, 32).
    gemm_packed<false><<<dim3(8, 32, 1), 128, SMEM_TOT>>>(
        (const float4*)hid, (const float4*)dnr, 0LL, nullptr, out, 1024);
}

// round 13
// speedup vs baseline: 2.7740x; 1.8241x over previous
// MoEExperts round 13: fp16 m16n8k16 (same 11-bit mantissa as tf32 -> same
// rounding error, 2x MMA throughput, half the operand bytes). Packed-fragment
// layouts: A-frag 16B/lane per 16x16 tile, B as n-pair tiles (16n x 16k,
// 16B/lane). CTA 128x128, 4 warps 64x64, BK=64, 2-stage cp.async, one
// __syncthreads/iter. silu*up*rw fused into k1 epilogue which emits hid
// directly in fp16 A-frag layout for k3. fp32 accumulate throughout.

#include <cuda_runtime.h>
#include <cuda_fp16.h>
#include <cstdint>

#define Tt 4096
#define Ee 8
#define Hh 1024
#define Qq 1024

// Packed fp16 scratch (uint4 = 8 halves = one lane-fragment).
__device__ uint4 g_xr [ 524288];   //  8 MB  x      [mt=256][kt= 64][lane]
__device__ uint4 g_w1p[2097152];   // 32 MB  W1     [e][npt=128][kt=64][lane]
__device__ uint4 g_dnr[1048576];   // 16 MB  down   [npt=64][kt=512][lane]
__device__ uint4 g_hid[4194304];   // 64 MB  hidden [mt=256][kt=512][lane]

// ---------------------------------------------------------------- helpers
__device__ __forceinline__ unsigned smem_u32(const void* p) {
    return (unsigned)__cvta_generic_to_shared(p);
}
__device__ __forceinline__ void cp_async16(unsigned s, const void* g) {
    asm volatile("cp.async.cg.shared.global [%0], [%1], 16;\n" :: "r"(s), "l"(g));
}
__device__ __forceinline__ void cp_commit() {
    asm volatile("cp.async.commit_group;\n");
}
template<int N>
__device__ __forceinline__ void cp_wait() {
    asm volatile("cp.async.wait_group %0;\n" :: "n"(N));
}
// pack two floats -> f16x2 (round-to-nearest), lo = first arg
__device__ __forceinline__ unsigned h2(float a, float b) {
    __half2 h = __floats2half2_rn(a, b);
    return *reinterpret_cast<unsigned*>(&h);
}
__device__ __forceinline__ void mma_f16(float* c, const uint4& a,
                                        unsigned b0, unsigned b1) {
    asm volatile(
        "mma.sync.aligned.m16n8k16.row.col.f32.f16.f16.f32 "
        "{%0,%1,%2,%3}, {%4,%5,%6,%7}, {%8,%9}, {%0,%1,%2,%3};\n"
        : "+f"(c[0]), "+f"(c[1]), "+f"(c[2]), "+f"(c[3])
        : "r"(a.x), "r"(a.y), "r"(a.z), "r"(a.w), "r"(b0), "r"(b1));
}

// ---------------------------------------------------------------- GEMM
// CTA 128m x 128n, BK=64 (4 k-tiles of 16). 4 warps 2x2, warp tile 64x64.
// Stage: A 8 mt x 4 kt x 512B = 16KB; B 8 npt x 4 kt x 512B = 16KB.
constexpr int STG      = 32768;
constexpr int SMEM_TOT = 2 * STG;          // 65,536 B -> 2 CTAs/SM

template<bool FUSE>
__global__ __launch_bounds__(128, 2)
void gemm_f16(const uint4* __restrict__ A,     // [mt][kt][lane]
              const uint4* __restrict__ B,     // [npt][kt][lane]
              long long sBe,                    // uint4 per expert (B)
              const float* __restrict__ rw,
              void* __restrict__ Cv,            // FUSE: uint4 hid; else float out
              int KT)                           // K/16 tiles
{
    extern __shared__ char smem[];

    const int tid = threadIdx.x;
    const int lane = tid & 31, warp = tid >> 5;
    const int wm = warp >> 1, wn = warp & 1;      // 2x2 warp grid
    const int gid = lane >> 2, tig = lane & 3;

    const int nb = blockIdx.x;               // n-block (128 cols = 8 npt)
    const int by = blockIdx.y;               // m-block (128 rows = 8 mt)
    const int e  = blockIdx.z;

    const uint4* Ab = A + (size_t)(by * 8) * KT * 32;
    const uint4* Bb = B + (size_t)e * sBe + (size_t)(nb * 8) * KT * 32;

    const int nIter = KT >> 2;               // 4 k-tiles (64 k) per iter

    auto load_stage = [&](int it, int slot) {
        char* sA = smem + slot * STG;
        char* sB = sA + 16384;
        const int ktg0 = it * 4;
        #pragma unroll
        for (int i = 0; i < 8; i++) {        // A: 1024 uint4
            const int c = tid + i * 128;
            const int mt = c >> 7, kt = (c >> 5) & 3, ln = c & 31;
            cp_async16(smem_u32(sA + ((mt * 4 + kt) * 32 + ln) * 16),
                       Ab + ((size_t)mt * KT + ktg0 + kt) * 32 + ln);
        }
        #pragma unroll
        for (int i = 0; i < 8; i++) {        // B: 1024 uint4
            const int c = tid + i * 128;
            const int nt = c >> 7, kt = (c >> 5) & 3, ln = c & 31;
            cp_async16(smem_u32(sB + ((nt * 4 + kt) * 32 + ln) * 16),
                       Bb + ((size_t)nt * KT + ktg0 + kt) * 32 + ln);
        }
        cp_commit();
    };

    float acc[4][8][4];
    #pragma unroll
    for (int im = 0; im < 4; im++)
        #pragma unroll
        for (int in = 0; in < 8; in++)
            #pragma unroll
            for (int v = 0; v < 4; v++) acc[im][in][v] = 0.f;

    load_stage(0, 0);

    for (int it = 0; it < nIter; ++it) {
        const int cur = it & 1;
        cp_wait<0>();
        __syncthreads();
        if (it + 1 < nIter) load_stage(it + 1, cur ^ 1);

        const char* sA = smem + cur * STG;
        const char* sB = sA + 16384;
        #pragma unroll
        for (int j = 0; j < 4; j++) {
            uint4 va[4], vb[4];
            #pragma unroll
            for (int im = 0; im < 4; im++)
                va[im] = *(const uint4*)(sA + (((wm * 4 + im) * 4 + j) * 32 + lane) * 16);
            #pragma unroll
            for (int p = 0; p < 4; p++)
                vb[p] = *(const uint4*)(sB + (((wn * 4 + p) * 4 + j) * 32 + lane) * 16);
            #pragma unroll
            for (int im = 0; im < 4; im++)
                #pragma unroll
                for (int p = 0; p < 4; p++) {
                    mma_f16(acc[im][2 * p],     va[im], vb[p].x, vb[p].y);
                    mma_f16(acc[im][2 * p + 1], va[im], vb[p].z, vb[p].w);
                }
        }
    }
    // Epilogue uses no shared memory.

    // acc[im][in]: rows by*128 + wm*64 + im*16 + gid (+8),
    // cols nb*128 + wn*64 + in*8 + {2tig, 2tig+1}.
    if constexpr (FUSE) {
        // 64-block = [gate32|up32] of q-range (nb*2+wn)*32; in<4 gate, in+4 up.
        #pragma unroll
        for (int im = 0; im < 4; im++) {
            const int r = wm * 64 + im * 16 + gid;
            const int t0 = by * 128 + r;
            const float w0 = rw[t0 * Ee + e];
            const float w1 = rw[(t0 + 8) * Ee + e];
            const size_t mt = (size_t)(by * 8 + wm * 4 + im);
            float hv[4][4];
            #pragma unroll
            for (int in = 0; in < 4; in++) {
                float g, u;
                g = acc[im][in][0]; u = acc[im][in + 4][0];
                hv[in][0] = w0 * u * (g / (1.f + __expf(-g)));
                g = acc[im][in][1]; u = acc[im][in + 4][1];
                hv[in][1] = w0 * u * (g / (1.f + __expf(-g)));
                g = acc[im][in][2]; u = acc[im][in + 4][2];
                hv[in][2] = w1 * u * (g / (1.f + __expf(-g)));
                g = acc[im][in][3]; u = acc[im][in + 4][3];
                hv[in][3] = w1 * u * (g / (1.f + __expf(-g)));
            }
            // Assemble two fp16 A-frags (k-tiles s=0,1) for k3:
            //   a0=(row g, k,k+1) a1=(row g+8) a2=(row g, k+8,k+9) a3=(row g+8)
            #pragma unroll
            for (int s = 0; s < 2; s++) {
                uint4 o;
                o.x = h2(hv[2 * s][0],     hv[2 * s][1]);
                o.y = h2(hv[2 * s][2],     hv[2 * s][3]);
                o.z = h2(hv[2 * s + 1][0], hv[2 * s + 1][1]);
                o.w = h2(hv[2 * s + 1][2], hv[2 * s + 1][3]);
                const size_t ktile = (size_t)(e * 64 + (nb * 2 + wn) * 2 + s);
                ((uint4*)Cv)[(mt * 512 + ktile) * 32 + lane] = o;
            }
        }
    } else {
        float* C = (float*)Cv;
        #pragma unroll
        for (int im = 0; im < 4; im++) {
            const int r = wm * 64 + im * 16 + gid;
            const int t0 = by * 128 + r;
            #pragma unroll
            for (int in = 0; in < 8; in++) {
                const int col = nb * 128 + wn * 64 + in * 8 + 2 * tig;
                *(float2*)&C[(size_t)t0 * Hh + col] =
                    make_float2(acc[im][in][0], acc[im][in][1]);
                *(float2*)&C[(size_t)(t0 + 8) * Hh + col] =
                    make_float2(acc[im][in][2], acc[im][in][3]);
            }
        }
    }
}

// ---------------------------------------------------------------- prepass
// pack_a: x (4096x1024) -> fp16 A-frags [mt=256][kt=64][lane].
__global__ void pack_a(const float* __restrict__ x, uint4* __restrict__ dst)
{
    const int idx = blockIdx.x * blockDim.x + threadIdx.x;   // 524288
    const int lane = idx & 31, kt = (idx >> 5) & 63, mt = idx >> 11;
    const int g = lane >> 2, t = lane & 3;
    const int m = mt * 16 + g, k = kt * 16 + 2 * t;
    const float* x0 = x + (size_t)m * 1024 + k;
    const float* x8 = x + (size_t)(m + 8) * 1024 + k;
    uint4 o;
    o.x = h2(x0[0], x0[1]);
    o.y = h2(x8[0], x8[1]);
    o.z = h2(x0[8], x0[9]);
    o.w = h2(x8[8], x8[9]);
    dst[idx] = o;
}

// pack_w1: gup (E,H,2Q) -> fp16 B n-pair frags in permuted n' space
// (n' 64-block = [gate32|up32]): [e][npt=128][kt=64][lane].
__global__ void pack_w1(const float* __restrict__ gup, uint4* __restrict__ dst)
{
    const int idx = blockIdx.x * blockDim.x + threadIdx.x;   // 2097152
    const int lane = idx & 31, kt = (idx >> 5) & 63, npt = (idx >> 11) & 127;
    const int e = idx >> 18;
    const int g = lane >> 2, t = lane & 3;
    const int k = kt * 16 + 2 * t;
    auto orig = [](int np) {
        const int b = np >> 6, i = np & 63;
        return (i < 32) ? b * 32 + i : 1024 + b * 32 + (i - 32);
    };
    const int nA = orig(npt * 16 + g);
    const int nB = orig(npt * 16 + 8 + g);
    const float* base = gup + ((size_t)e * 1024 + k) * 2048;   // row stride 2048
    uint4 o;
    o.x = h2(base[nA],            base[2048 + nA]);            // k, k+1 @ nA
    o.y = h2(base[8 * 2048 + nA], base[9 * 2048 + nA]);        // k+8,k+9 @ nA
    o.z = h2(base[nB],            base[2048 + nB]);
    o.w = h2(base[8 * 2048 + nB], base[9 * 2048 + nB]);
    dst[idx] = o;
}

// pack_dn: down (E,Q,H) flattened (8192 x 1024) -> fp16 B n-pair frags
// [npt=64][kt=512][lane] (k = e*1024+q).
__global__ void pack_dn(const float* __restrict__ dn, uint4* __restrict__ dst)
{
    const int idx = blockIdx.x * blockDim.x + threadIdx.x;   // 1048576
    const int lane = idx & 31, kt = (idx >> 5) & 511, npt = idx >> 14;
    const int g = lane >> 2, t = lane & 3;
    const int k = kt * 16 + 2 * t;
    const int n = npt * 16 + g;
    const float* base = dn + (size_t)k * 1024 + n;
    uint4 o;
    o.x = h2(base[0],            base[1024]);
    o.y = h2(base[8 * 1024],     base[9 * 1024]);
    o.z = h2(base[8],            base[1024 + 8]);
    o.w = h2(base[8 * 1024 + 8], base[9 * 1024 + 8]);
    dst[idx] = o;
}

// ---------------------------------------------------------------- launch
extern "C" void kernel_launch(void* const* d_in, const int* in_sizes, int n_in,
                              void* d_out, int out_size)
{
    (void)in_sizes; (void)n_in; (void)out_size;
    const float* x    = (const float*)d_in[0];   // (T, H)
    const float* rw   = (const float*)d_in[1];   // (T, E)
    const float* gup  = (const float*)d_in[2];   // (E, H, 2Q)
    const float* down = (const float*)d_in[3];   // (E, Q, H)
    float* out = (float*)d_out;                  // (T, H)

    uint4 *xr, *w1p, *dnr, *hid;
    cudaGetSymbolAddress((void**)&xr,  g_xr);
    cudaGetSymbolAddress((void**)&w1p, g_w1p);
    cudaGetSymbolAddress((void**)&dnr, g_dnr);
    cudaGetSymbolAddress((void**)&hid, g_hid);

    cudaFuncSetAttribute(gemm_f16<true>,
                         cudaFuncAttributeMaxDynamicSharedMemorySize, SMEM_TOT);
    cudaFuncSetAttribute(gemm_f16<false>,
                         cudaFuncAttributeMaxDynamicSharedMemorySize, SMEM_TOT);

    pack_a <<<2048, 256>>>(x, xr);
    pack_w1<<<8192, 256>>>(gup, w1p);
    pack_dn<<<4096, 256>>>(down, dnr);

    // k1: hidden = rw * silu(gate) * up (fused, fp16 A-frag store). KT=64.
    // grid: 16 n-blocks x 32 m-blocks x 8 experts; B expert stride 128*64*32.
    gemm_f16<true><<<dim3(16, 32, 8), 128, SMEM_TOT>>>(
        xr, w1p, 262144LL, rw, hid, 64);

    // k3: out = hid(4096x8192) @ dnr^T. KT=512. grid (8, 32) = 256 CTAs
    // (fully resident in one wave at 2 CTAs/SM).
    gemm_f16<false><<<dim3(8, 32, 1), 128, SMEM_TOT>>>(
        hid, dnr, 0LL, nullptr, out, 512);
}

// round 15
// speedup vs baseline: 2.8677x; 1.0338x over previous
// MoEExperts round 15: fp16 m16n8k16 packed-fragment GEMM, 4-stage x 16KB
// cp.async pipeline (cp_wait<2>: awaited load issued THREE compute spans
// before use) inside the empirically-proven 64KB smem envelope (all >=96KB
// submissions died; all <=64KB passed). Per-iteration fragment hoist: all 16
// LDS.128 issued before the 64 MMAs. CTA 128x128, 4 warps 64x64, register-
// local fused silu epilogue emitting hid in fp16 A-frag layout, fp32 accum.

#include <cuda_runtime.h>
#include <cuda_fp16.h>
#include <cstdint>

#define Tt 4096
#define Ee 8
#define Hh 1024
#define Qq 1024

// Packed fp16 scratch (uint4 = 8 halves = one lane-fragment).
__device__ uint4 g_xr [ 524288];   //  8 MB  x      [mt=256][kt= 64][lane]
__device__ uint4 g_w1p[2097152];   // 32 MB  W1     [e][npt=128][kt=64][lane]
__device__ uint4 g_dnr[1048576];   // 16 MB  down   [npt=64][kt=512][lane]
__device__ uint4 g_hid[4194304];   // 64 MB  hidden [mt=256][kt=512][lane]

// ---------------------------------------------------------------- helpers
__device__ __forceinline__ unsigned smem_u32(const void* p) {
    return (unsigned)__cvta_generic_to_shared(p);
}
__device__ __forceinline__ void cp_async16(unsigned s, const void* g) {
    asm volatile("cp.async.cg.shared.global [%0], [%1], 16;\n" :: "r"(s), "l"(g));
}
__device__ __forceinline__ void cp_commit() {
    asm volatile("cp.async.commit_group;\n");
}
template<int N>
__device__ __forceinline__ void cp_wait() {
    asm volatile("cp.async.wait_group %0;\n" :: "n"(N));
}
// pack two floats -> f16x2 (round-to-nearest), lo = first arg
__device__ __forceinline__ unsigned h2(float a, float b) {
    __half2 h = __floats2half2_rn(a, b);
    return *reinterpret_cast<unsigned*>(&h);
}
__device__ __forceinline__ void mma_f16(float* c, const uint4& a,
                                        unsigned b0, unsigned b1) {
    asm volatile(
        "mma.sync.aligned.m16n8k16.row.col.f32.f16.f16.f32 "
        "{%0,%1,%2,%3}, {%4,%5,%6,%7}, {%8,%9}, {%0,%1,%2,%3};\n"
        : "+f"(c[0]), "+f"(c[1]), "+f"(c[2]), "+f"(c[3])
        : "r"(a.x), "r"(a.y), "r"(a.z), "r"(a.w), "r"(b0), "r"(b1));
}

// ---------------------------------------------------------------- GEMM
// CTA 128m x 128n. Stage = BK 32 (2 k-tiles of 16): A 8mt x 2kt x 512B = 8KB,
// B 8npt x 2kt x 512B = 8KB -> 16KB/stage, 4 stages = 64KB. 4 warps 2x2,
// warp tile 64x64.
constexpr int STAGES   = 4;
constexpr int STG      = 16384;
constexpr int SMEM_TOT = STAGES * STG;     // 65,536 B

template<bool FUSE>
__global__ __launch_bounds__(128, 2)
void gemm_f16(const uint4* __restrict__ A,     // [mt][kt][lane]
              const uint4* __restrict__ B,     // [npt][kt][lane]
              long long sBe,                    // uint4 per expert (B)
              const float* __restrict__ rw,
              void* __restrict__ Cv,            // FUSE: uint4 hid; else float out
              int KT)                           // K/16 tiles
{
    extern __shared__ char smem[];

    const int tid = threadIdx.x;
    const int lane = tid & 31, warp = tid >> 5;
    const int wm = warp >> 1, wn = warp & 1;      // 2x2 warp grid
    const int gid = lane >> 2, tig = lane & 3;

    const int nb = blockIdx.x;               // n-block (128 cols = 8 npt)
    const int by = blockIdx.y;               // m-block (128 rows = 8 mt)
    const int e  = blockIdx.z;

    const uint4* Ab = A + (size_t)(by * 8) * KT * 32;
    const uint4* Bb = B + (size_t)e * sBe + (size_t)(nb * 8) * KT * 32;

    const int nIter = KT >> 1;               // 2 k-tiles (32 k) per iter

    auto load_stage = [&](int it) {
        char* sA = smem + (it & (STAGES - 1)) * STG;
        char* sB = sA + 8192;
        const int ktg0 = it * 2;
        #pragma unroll
        for (int i = 0; i < 4; i++) {        // A: 512 uint4
            const int c = tid + i * 128;
            const int mt = c >> 6, kt = (c >> 5) & 1, ln = c & 31;
            cp_async16(smem_u32(sA + ((mt * 2 + kt) * 32 + ln) * 16),
                       Ab + ((size_t)mt * KT + ktg0 + kt) * 32 + ln);
        }
        #pragma unroll
        for (int i = 0; i < 4; i++) {        // B: 512 uint4
            const int c = tid + i * 128;
            const int nt = c >> 6, kt = (c >> 5) & 1, ln = c & 31;
            cp_async16(smem_u32(sB + ((nt * 2 + kt) * 32 + ln) * 16),
                       Bb + ((size_t)nt * KT + ktg0 + kt) * 32 + ln);
        }
        cp_commit();
    };

    float acc[4][8][4];
    #pragma unroll
    for (int im = 0; im < 4; im++)
        #pragma unroll
        for (int in = 0; in < 8; in++)
            #pragma unroll
            for (int v = 0; v < 4; v++) acc[im][in][v] = 0.f;

    load_stage(0);
    load_stage(1);
    load_stage(2);

    for (int it = 0; it < nIter; ++it) {
        // complete stage `it`; keep up to 2 younger loads in flight
        if      (it + 2 < nIter) cp_wait<2>();
        else if (it + 1 < nIter) cp_wait<1>();
        else                     cp_wait<0>();
        __syncthreads();                     // all warps done with slot (it-1)%4
        if (it + 3 < nIter) load_stage(it + 3);

        const char* sA = smem + (it & (STAGES - 1)) * STG;
        const char* sB = sA + 8192;

        // hoist ALL fragment loads of this iteration ahead of the MMAs
        uint4 va[2][4], vb[2][4];
        #pragma unroll
        for (int j = 0; j < 2; j++) {
            #pragma unroll
            for (int im = 0; im < 4; im++)
                va[j][im] = *(const uint4*)(sA + (((wm * 4 + im) * 2 + j) * 32 + lane) * 16);
            #pragma unroll
            for (int p = 0; p < 4; p++)
                vb[j][p] = *(const uint4*)(sB + (((wn * 4 + p) * 2 + j) * 32 + lane) * 16);
        }
        #pragma unroll
        for (int j = 0; j < 2; j++)
            #pragma unroll
            for (int im = 0; im < 4; im++)
                #pragma unroll
                for (int p = 0; p < 4; p++) {
                    mma_f16(acc[im][2 * p],     va[j][im], vb[j][p].x, vb[j][p].y);
                    mma_f16(acc[im][2 * p + 1], va[j][im], vb[j][p].z, vb[j][p].w);
                }
    }
    // Epilogue uses no shared memory.

    // acc[im][in]: rows by*128 + wm*64 + im*16 + gid (+8),
    // cols nb*128 + wn*64 + in*8 + {2tig, 2tig+1}.
    if constexpr (FUSE) {
        // 64-block = [gate32|up32] of q-range (nb*2+wn)*32; in<4 gate, in+4 up.
        #pragma unroll
        for (int im = 0; im < 4; im++) {
            const int r = wm * 64 + im * 16 + gid;
            const int t0 = by * 128 + r;
            const float w0 = rw[t0 * Ee + e];
            const float w1 = rw[(t0 + 8) * Ee + e];
            const size_t mt = (size_t)(by * 8 + wm * 4 + im);
            float hv[4][4];
            #pragma unroll
            for (int in = 0; in < 4; in++) {
                float g, u;
                g = acc[im][in][0]; u = acc[im][in + 4][0];
                hv[in][0] = w0 * u * (g / (1.f + __expf(-g)));
                g = acc[im][in][1]; u = acc[im][in + 4][1];
                hv[in][1] = w0 * u * (g / (1.f + __expf(-g)));
                g = acc[im][in][2]; u = acc[im][in + 4][2];
                hv[in][2] = w1 * u * (g / (1.f + __expf(-g)));
                g = acc[im][in][3]; u = acc[im][in + 4][3];
                hv[in][3] = w1 * u * (g / (1.f + __expf(-g)));
            }
            // two fp16 A-frags (k-tiles s=0,1) for k3
            #pragma unroll
            for (int s = 0; s < 2; s++) {
                uint4 o;
                o.x = h2(hv[2 * s][0],     hv[2 * s][1]);
                o.y = h2(hv[2 * s][2],     hv[2 * s][3]);
                o.z = h2(hv[2 * s + 1][0], hv[2 * s + 1][1]);
                o.w = h2(hv[2 * s + 1][2], hv[2 * s + 1][3]);
                const size_t ktile = (size_t)(e * 64 + (nb * 2 + wn) * 2 + s);
                ((uint4*)Cv)[(mt * 512 + ktile) * 32 + lane] = o;
            }
        }
    } else {
        float* C = (float*)Cv;
        #pragma unroll
        for (int im = 0; im < 4; im++) {
            const int r = wm * 64 + im * 16 + gid;
            const int t0 = by * 128 + r;
            #pragma unroll
            for (int in = 0; in < 8; in++) {
                const int col = nb * 128 + wn * 64 + in * 8 + 2 * tig;
                *(float2*)&C[(size_t)t0 * Hh + col] =
                    make_float2(acc[im][in][0], acc[im][in][1]);
                *(float2*)&C[(size_t)(t0 + 8) * Hh + col] =
                    make_float2(acc[im][in][2], acc[im][in][3]);
            }
        }
    }
}

// ---------------------------------------------------------------- prepass
// pack_a: x (4096x1024) -> fp16 A-frags [mt=256][kt=64][lane].
__global__ void pack_a(const float* __restrict__ x, uint4* __restrict__ dst)
{
    const int idx = blockIdx.x * blockDim.x + threadIdx.x;   // 524288
    const int lane = idx & 31, kt = (idx >> 5) & 63, mt = idx >> 11;
    const int g = lane >> 2, t = lane & 3;
    const int m = mt * 16 + g, k = kt * 16 + 2 * t;
    const float* x0 = x + (size_t)m * 1024 + k;
    const float* x8 = x + (size_t)(m + 8) * 1024 + k;
    uint4 o;
    o.x = h2(x0[0], x0[1]);
    o.y = h2(x8[0], x8[1]);
    o.z = h2(x0[8], x0[9]);
    o.w = h2(x8[8], x8[9]);
    dst[idx] = o;
}

// pack_w1: gup (E,H,2Q) -> fp16 B n-pair frags in permuted n' space
// (n' 64-block = [gate32|up32]): [e][npt=128][kt=64][lane].
__global__ void pack_w1(const float* __restrict__ gup, uint4* __restrict__ dst)
{
    const int idx = blockIdx.x * blockDim.x + threadIdx.x;   // 2097152
    const int lane = idx & 31, kt = (idx >> 5) & 63, npt = (idx >> 11) & 127;
    const int e = idx >> 18;
    const int g = lane >> 2, t = lane & 3;
    const int k = kt * 16 + 2 * t;
    auto orig = [](int np) {
        const int b = np >> 6, i = np & 63;
        return (i < 32) ? b * 32 + i : 1024 + b * 32 + (i - 32);
    };
    const int nA = orig(npt * 16 + g);
    const int nB = orig(npt * 16 + 8 + g);
    const float* base = gup + ((size_t)e * 1024 + k) * 2048;   // row stride 2048
    uint4 o;
    o.x = h2(base[nA],            base[2048 + nA]);            // k, k+1 @ nA
    o.y = h2(base[8 * 2048 + nA], base[9 * 2048 + nA]);        // k+8,k+9 @ nA
    o.z = h2(base[nB],            base[2048 + nB]);
    o.w = h2(base[8 * 2048 + nB], base[9 * 2048 + nB]);
    dst[idx] = o;
}

// pack_dn: down (E,Q,H) flattened (8192 x 1024) -> fp16 B n-pair frags
// [npt=64][kt=512][lane] (k = e*1024+q).
__global__ void pack_dn(const float* __restrict__ dn, uint4* __restrict__ dst)
{
    const int idx = blockIdx.x * blockDim.x + threadIdx.x;   // 1048576
    const int lane = idx & 31, kt = (idx >> 5) & 511, npt = idx >> 14;
    const int g = lane >> 2, t = lane & 3;
    const int k = kt * 16 + 2 * t;
    const int n = npt * 16 + g;
    const float* base = dn + (size_t)k * 1024 + n;
    uint4 o;
    o.x = h2(base[0],            base[1024]);
    o.y = h2(base[8 * 1024],     base[9 * 1024]);
    o.z = h2(base[8],            base[1024 + 8]);
    o.w = h2(base[8 * 1024 + 8], base[9 * 1024 + 8]);
    dst[idx] = o;
}

// ---------------------------------------------------------------- launch
extern "C" void kernel_launch(void* const* d_in, const int* in_sizes, int n_in,
                              void* d_out, int out_size)
{
    (void)in_sizes; (void)n_in; (void)out_size;
    const float* x    = (const float*)d_in[0];   // (T, H)
    const float* rw   = (const float*)d_in[1];   // (T, E)
    const float* gup  = (const float*)d_in[2];   // (E, H, 2Q)
    const float* down = (const float*)d_in[3];   // (E, Q, H)
    float* out = (float*)d_out;                  // (T, H)

    uint4 *xr, *w1p, *dnr, *hid;
    cudaGetSymbolAddress((void**)&xr,  g_xr);
    cudaGetSymbolAddress((void**)&w1p, g_w1p);
    cudaGetSymbolAddress((void**)&dnr, g_dnr);
    cudaGetSymbolAddress((void**)&hid, g_hid);

    cudaFuncSetAttribute(gemm_f16<true>,
                         cudaFuncAttributeMaxDynamicSharedMemorySize, SMEM_TOT);
    cudaFuncSetAttribute(gemm_f16<false>,
                         cudaFuncAttributeMaxDynamicSharedMemorySize, SMEM_TOT);

    pack_a <<<2048, 256>>>(x, xr);
    pack_w1<<<8192, 256>>>(gup, w1p);
    pack_dn<<<4096, 256>>>(down, dnr);

    // k1: hidden = rw * silu(gate) * up (fused, fp16 A-frag store). KT=64.
    gemm_f16<true><<<dim3(16, 32, 8), 128, SMEM_TOT>>>(
        xr, w1p, 262144LL, rw, hid, 64);

    // k3: out = hid(4096x8192) @ dnr^T. KT=512. grid (8, 32) = 256 CTAs.
    gemm_f16<false><<<dim3(8, 32, 1), 128, SMEM_TOT>>>(
        hid, dnr, 0LL, nullptr, out, 512);
}